// round 5
// baseline (speedup 1.0000x reference)
#include <cuda_runtime.h>
#include <stdint.h>

#define BB 4
#define SS 2048
#define DD 1024
#define EE 64
#define CC 64
#define ROWS (BB*SS)          // 8192
#define NOISE_SCALE (1.0f/64.0f)
#define HALF ((size_t)BB*SS*EE*CC)      // elements per output array
#define TOTAL_F4 ((2*HALF)/4)           // 16,777,216 float4 of output

#define NZERO   40                       // zero blocks (<=1 per SM)
#define NGEMM   256                      // gemm blocks, 32 rows each
#define FAT_GRID (NZERO + NGEMM)         // 296 = 2 * 148
#define ZCHUNK  393216                   // float4 per zero block
#define GCHUNK  4096                     // float4 tail per gemm block
#define ZBASE   ((size_t)NZERO * ZCHUNK) // 15,728,640

// Scratch: gates transposed [b][e][s]  (2 MB)
__device__ float g_gatesT[(size_t)BB*EE*SS];

// ---------------------------------------------------------------------------
// Fat kernel: blocks 0..39 zero-fill ~94% of the 268MB output (DRAM-bound,
// warps mostly stalled on store backpressure -> few issue slots consumed).
// Blocks 40..295 each compute a 32-row x 64-expert GEMM tile + noise +
// softmax, then zero a small tail chunk. Grid = 296 = 2 blocks/SM, so at most
// ONE zero block shares an SM with a gemm block.
// ---------------------------------------------------------------------------
__global__ __launch_bounds__(256)
void fat_gemm_zero_kernel(const float* __restrict__ X,
                          const float* __restrict__ W,
                          const float* __restrict__ noise,
                          float4* __restrict__ out4)
{
    const int tid = threadIdx.x;

    if (blockIdx.x < NZERO) {
        // ---- zero path: coalesced strided float4 fill ----
        const float4 z = make_float4(0.f, 0.f, 0.f, 0.f);
        size_t base = (size_t)blockIdx.x * ZCHUNK + tid;
#pragma unroll 4
        for (int q = 0; q < ZCHUNK / 256; q++)
            out4[base + (size_t)q * 256] = z;
        return;
    }

    // ---- gemm path ----
    __shared__ float As[32][66];   // [row][k]  (8.4KB; 66 even -> float2 aligned)
    __shared__ float Ws[64][64];   // [k][expert] (16KB); rows 0..31 reused for logits

    const int g    = blockIdx.x - NZERO;       // 0..255
    const int tx   = tid & 15;                 // expert group (4 experts)
    const int ty   = tid >> 4;                 // row group (2 rows)
    const int row0 = g * 32;

    float acc[2][4];
#pragma unroll
    for (int i = 0; i < 2; i++)
#pragma unroll
        for (int j = 0; j < 4; j++) acc[i][j] = 0.0f;

    for (int k0 = 0; k0 < DD; k0 += 64) {
        // A tile: 32 rows x 64 k  (512 float4, 2 per thread)
#pragma unroll
        for (int p = 0; p < 2; p++) {
            int r  = (tid >> 4) + p * 16;
            int kv = (tid & 15) * 4;
            float4 v = *(const float4*)&X[(size_t)(row0 + r) * DD + k0 + kv];
            As[r][kv + 0] = v.x;
            As[r][kv + 1] = v.y;
            As[r][kv + 2] = v.z;
            As[r][kv + 3] = v.w;
        }
        // W tile: 64 k x 64 experts (1024 float4, 4 per thread)
#pragma unroll
        for (int p = 0; p < 4; p++) {
            int kk = (tid >> 4) + p * 16;
            int ev = (tid & 15) * 4;
            *(float4*)&Ws[kk][ev] = *(const float4*)&W[(size_t)(k0 + kk) * EE + ev];
        }
        __syncthreads();

#pragma unroll
        for (int kk = 0; kk < 64; kk += 2) {
            float4 b0 = *(const float4*)&Ws[kk + 0][tx * 4];
            float4 b1 = *(const float4*)&Ws[kk + 1][tx * 4];
#pragma unroll
            for (int i = 0; i < 2; i++) {
                float2 a = *(const float2*)&As[ty * 2 + i][kk];
                acc[i][0] += a.x * b0.x; acc[i][1] += a.x * b0.y;
                acc[i][2] += a.x * b0.z; acc[i][3] += a.x * b0.w;
                acc[i][0] += a.y * b1.x; acc[i][1] += a.y * b1.y;
                acc[i][2] += a.y * b1.z; acc[i][3] += a.y * b1.w;
            }
        }
        __syncthreads();
    }

    // Epilogue: logits + noise into Ws rows 0..31
#pragma unroll
    for (int i = 0; i < 2; i++) {
        int r   = ty * 2 + i;
        int row = row0 + r;
#pragma unroll
        for (int j = 0; j < 4; j++) {
            int e = tx * 4 + j;
            Ws[r][e] = acc[i][j] + noise[(size_t)row * EE + e] * NOISE_SCALE;
        }
    }
    __syncthreads();

    // Softmax per row (threads 0..31), write transposed gates.
    if (tid < 32) {
        int r   = tid;
        int row = row0 + r;
        int b   = row / SS;
        int s   = row % SS;
        float m = -1e30f;
#pragma unroll
        for (int e = 0; e < EE; e++) m = fmaxf(m, Ws[r][e]);
        float sum = 0.0f;
#pragma unroll
        for (int e = 0; e < EE; e++) {
            float t = expf(Ws[r][e] - m);
            Ws[r][e] = t;
            sum += t;
        }
        float inv = 1.0f / sum;
#pragma unroll
        for (int e = 0; e < EE; e++) {
            g_gatesT[((size_t)b * EE + e) * SS + s] = Ws[r][e] * inv;
        }
    }

    // Tail zero chunk (independent of smem; no sync needed)
    {
        const float4 z = make_float4(0.f, 0.f, 0.f, 0.f);
        size_t base = ZBASE + (size_t)g * GCHUNK + tid;
#pragma unroll
        for (int q = 0; q < GCHUNK / 256; q++)
            out4[base + (size_t)q * 256] = z;
    }
}

// ---------------------------------------------------------------------------
// Kernel 2: per-(b,e) exact top-64 via MSD radix select on u64 keys
// (gate_bits<<32)|~idx (distinct), parallel suffix-scan digit selection,
// then ADAPTIVE bitonic sort of the candidate set for exact rank order.
// Grid: 256 blocks (b*64+e), 512 threads.
// ---------------------------------------------------------------------------
__global__ __launch_bounds__(512, 2)
void topk_kernel(float* __restrict__ mask_out,
                 float* __restrict__ comb_out)
{
    __shared__ unsigned long long keys[SS];
    __shared__ unsigned long long cand[512];
    __shared__ int hist[256];
    __shared__ unsigned long long s_prefix, s_thresh;
    __shared__ int s_need, s_done, s_cnt;

    const int tid = threadIdx.x;
    const int b = blockIdx.x >> 6;
    const int e = blockIdx.x & 63;

    const float* col = &g_gatesT[((size_t)b * EE + e) * SS];
    for (int i = tid; i < SS; i += 512) {
        unsigned int fb = __float_as_uint(col[i]);   // softmax gates > 0
        keys[i] = ((unsigned long long)fb << 32) | (unsigned int)(~i);
    }
    if (tid == 0) { s_done = 0; s_need = CC; s_prefix = 0ULL; }
    __syncthreads();

    // MSD radix select, 8-bit digits. Exits when candidate set <= 512.
    for (int shift = 56; shift >= 0; shift -= 8) {
        if (s_done) break;
        const unsigned long long pf = s_prefix;   // stable snapshot
        const int need = s_need;
        if (tid < 256) hist[tid] = 0;
        __syncthreads();
        for (int i = tid; i < SS; i += 512) {
            unsigned long long k = keys[i];
            bool active = (shift == 56) || ((k >> (shift + 8)) == pf);
            if (active) atomicAdd(&hist[(int)((k >> shift) & 255)], 1);
        }
        __syncthreads();

        // Parallel suffix sum over 256 bins (Hillis-Steele, 8 rounds).
#pragma unroll
        for (int off = 1; off < 256; off <<= 1) {
            int v = 0;
            if (tid < 256) {
                v = hist[tid];
                if (tid + off < 256) v += hist[tid + off];
            }
            __syncthreads();
            if (tid < 256) hist[tid] = v;
            __syncthreads();
        }

        // Exactly one bin d satisfies sfx[d] >= need > sfx[d+1].
        if (tid < 256) {
            int c     = hist[tid];
            int above = (tid == 255) ? 0 : hist[tid + 1];
            if (c >= need && above < need) {
                int got = (CC - need) + c;          // keys >= boundary, globally
                unsigned long long np = (pf << 8) | (unsigned long long)tid;
                if (got <= 512 || shift == 0) {
                    s_thresh = np << shift;
                    s_done = 1;
                } else {
                    s_need = need - above;
                    s_prefix = np;
                }
            }
        }
        __syncthreads();
    }

    // Collect candidates (>= threshold); pad with 0 (all real keys > 0).
    cand[tid & 511] = 0ULL;
    if (tid == 0) s_cnt = 0;
    __syncthreads();
    {
        const unsigned long long T = s_thresh;
        for (int i = tid; i < SS; i += 512) {
            unsigned long long k = keys[i];
            if (k >= T) { int p = atomicAdd(&s_cnt, 1); if (p < 512) cand[p] = k; }
        }
    }
    __syncthreads();

    // Adaptive bitonic sort (descending): nsort = next pow2 >= max(cnt, 64).
    int cnt = s_cnt;
    int nsort = 64;
    while (nsort < cnt && nsort < 512) nsort <<= 1;

    for (int k2 = 2; k2 <= nsort; k2 <<= 1) {
        for (int j = k2 >> 1; j > 0; j >>= 1) {
            if (tid < (nsort >> 1)) {
                int i   = ((tid & ~(j - 1)) << 1) | (tid & (j - 1));
                int ixj = i | j;
                bool desc = ((i & k2) == 0);
                unsigned long long a = cand[i];
                unsigned long long c = cand[ixj];
                if ((a < c) == desc) { cand[i] = c; cand[ixj] = a; }
            }
            __syncthreads();
        }
    }

    // Scatter top-64 (rank = c)
    if (tid < CC) {
        unsigned long long k = cand[tid];
        int   s = (int)(~(unsigned int)k);
        float v = __uint_as_float((unsigned int)(k >> 32));
        size_t idx = ((((size_t)b * SS + s) * EE + e) << 6) + tid;
        mask_out[idx] = 1.0f;
        comb_out[idx] = v;
    }
}

// ---------------------------------------------------------------------------
extern "C" void kernel_launch(void* const* d_in, const int* in_sizes, int n_in,
                              void* d_out, int out_size)
{
    const float* X     = (const float*)d_in[0];   // [B,S,D]
    const float* W     = (const float*)d_in[1];   // [D,E]
    const float* noise = (const float*)d_in[2];   // [B,S,E]
    float* out = (float*)d_out;

    fat_gemm_zero_kernel<<<FAT_GRID, 256>>>(X, W, noise, (float4*)out);
    topk_kernel<<<BB * EE, 512>>>(out, out + HALF);
}

// round 6
// speedup vs baseline: 1.2259x; 1.2259x over previous
#include <cuda_runtime.h>
#include <stdint.h>

#define BB 4
#define SS 2048
#define DD 1024
#define EE 64
#define CC 64
#define ROWS (BB*SS)          // 8192
#define NOISE_SCALE (1.0f/64.0f)
#define HALF ((size_t)BB*SS*EE*CC)      // elements per output array
#define TOTAL_F4 ((2*HALF)/4)           // 16,777,216 float4 of output

#define GBLOCKS 128                      // gemm blocks (64 rows each)
#define ZF4_PER_BLOCK (TOTAL_F4/GBLOCKS) // 131072 float4 (2MB) per block
#define ZF4_PER_ITER  (ZF4_PER_BLOCK/16/256)  // 32 STG.128 per thread per outer-k iter

// Scratch: gates transposed [b][e][s]  (2 MB)
__device__ float g_gatesT[(size_t)BB*EE*SS];

__device__ __forceinline__ float2 ffma2(float2 a, float2 b, float2 c) {
    unsigned long long au = *reinterpret_cast<unsigned long long*>(&a);
    unsigned long long bu = *reinterpret_cast<unsigned long long*>(&b);
    unsigned long long cu = *reinterpret_cast<unsigned long long*>(&c);
    unsigned long long du;
    asm("fma.rn.f32x2 %0, %1, %2, %3;" : "=l"(du) : "l"(au), "l"(bu), "l"(cu));
    return *reinterpret_cast<float2*>(&du);
}

// ---------------------------------------------------------------------------
// Kernel 1: f32x2 GEMM + noise + softmax -> gatesT, with the FULL 268MB
// output zero-fill trickled through the k-loop (32 STG.128 per thread per
// outer iteration; fire-and-forget stores drain under ~1000 cycles of FFMA).
// Grid: 128 blocks x 256 threads, 64 rows x 64 experts per block.
// ---------------------------------------------------------------------------
__global__ __launch_bounds__(256, 1)
void gemm_zero_softmax_kernel(const float* __restrict__ X,
                              const float* __restrict__ W,
                              const float* __restrict__ noise,
                              float4* __restrict__ out4)
{
    __shared__ float2 As2[64][64];   // [row][k], value splat into both lanes (32KB)
    __shared__ float  Ws[64][64];    // [k][expert] (16KB); reused for logits

    const int tid  = threadIdx.x;
    const int tx   = tid & 15;       // expert group (4 experts)
    const int ty   = tid >> 4;       // row group (4 rows)
    const int row0 = blockIdx.x * 64;
    const float4 zf4 = make_float4(0.f, 0.f, 0.f, 0.f);
    const size_t zbase = (size_t)blockIdx.x * ZF4_PER_BLOCK + tid;

    float2 acc[4][2];
#pragma unroll
    for (int i = 0; i < 4; i++) {
        acc[i][0] = make_float2(0.f, 0.f);
        acc[i][1] = make_float2(0.f, 0.f);
    }

    for (int k0 = 0; k0 < DD; k0 += 64) {
        // A tile: 64 rows x 64 k, splat-stored as float2
#pragma unroll
        for (int p = 0; p < 4; p++) {
            int r  = (tid >> 4) + p * 16;
            int kv = (tid & 15) * 4;
            float4 v = *(const float4*)&X[(size_t)(row0 + r) * DD + k0 + kv];
            As2[r][kv + 0] = make_float2(v.x, v.x);
            As2[r][kv + 1] = make_float2(v.y, v.y);
            As2[r][kv + 2] = make_float2(v.z, v.z);
            As2[r][kv + 3] = make_float2(v.w, v.w);
        }
        // W tile: 64 k x 64 experts
#pragma unroll
        for (int p = 0; p < 4; p++) {
            int kk = (tid >> 4) + p * 16;
            int ev = (tid & 15) * 4;
            *(float4*)&Ws[kk][ev] = *(const float4*)&W[(size_t)(k0 + kk) * EE + ev];
        }
        __syncthreads();

        // Trickled zero-fill: 32 coalesced STG.128 per thread, posted before
        // the FFMA burst so they drain to DRAM while we compute.
        {
            const int o = k0 >> 6;   // outer iter 0..15
            size_t zb = zbase + (size_t)o * (ZF4_PER_ITER * 256);
#pragma unroll
            for (int q = 0; q < ZF4_PER_ITER; q++)
                out4[zb + q * 256] = zf4;
        }

#pragma unroll
        for (int kk = 0; kk < 64; kk++) {
            float4 bv = *(const float4*)&Ws[kk][tx * 4];
            float2 b01 = make_float2(bv.x, bv.y);
            float2 b23 = make_float2(bv.z, bv.w);
#pragma unroll
            for (int i = 0; i < 4; i++) {
                float2 a = As2[ty * 4 + i][kk];
                acc[i][0] = ffma2(a, b01, acc[i][0]);
                acc[i][1] = ffma2(a, b23, acc[i][1]);
            }
        }
        __syncthreads();
    }

    // Epilogue: logits + noise into Ws (reused as [row][expert])
#pragma unroll
    for (int i = 0; i < 4; i++) {
        int r   = ty * 4 + i;
        int row = row0 + r;
#pragma unroll
        for (int j = 0; j < 2; j++) {
            int e0 = tx * 4 + j * 2;
            float2 v = acc[i][j];
            Ws[r][e0 + 0] = v.x + noise[(size_t)row * EE + e0 + 0] * NOISE_SCALE;
            Ws[r][e0 + 1] = v.y + noise[(size_t)row * EE + e0 + 1] * NOISE_SCALE;
        }
    }
    __syncthreads();

    // Softmax per row (threads 0..63), write transposed gates.
    if (tid < 64) {
        int r   = tid;
        int row = row0 + r;
        int b   = row / SS;
        int s   = row % SS;
        float m = -1e30f;
#pragma unroll
        for (int e = 0; e < EE; e++) m = fmaxf(m, Ws[r][e]);
        float sum = 0.0f;
#pragma unroll
        for (int e = 0; e < EE; e++) {
            float t = expf(Ws[r][e] - m);
            Ws[r][e] = t;
            sum += t;
        }
        float inv = 1.0f / sum;
#pragma unroll
        for (int e = 0; e < EE; e++) {
            g_gatesT[((size_t)b * EE + e) * SS + s] = Ws[r][e] * inv;
        }
    }
}

// ---------------------------------------------------------------------------
// Kernel 2: per-(b,e) exact top-64 via MSD radix select on u64 keys
// (gate_bits<<32)|~idx (distinct), parallel suffix-scan digit selection,
// adaptive bitonic sort of candidates, scatter. (Output already zeroed by
// kernel 1 -> no race.) Grid: 256 blocks, 512 threads.
// ---------------------------------------------------------------------------
__global__ __launch_bounds__(512, 2)
void topk_kernel(float* __restrict__ mask_out,
                 float* __restrict__ comb_out)
{
    __shared__ unsigned long long keys[SS];
    __shared__ unsigned long long cand[512];
    __shared__ int hist[256];
    __shared__ unsigned long long s_prefix, s_thresh;
    __shared__ int s_need, s_done, s_cnt;

    const int tid = threadIdx.x;
    const int b = blockIdx.x >> 6;
    const int e = blockIdx.x & 63;

    const float* col = &g_gatesT[((size_t)b * EE + e) * SS];
    for (int i = tid; i < SS; i += 512) {
        unsigned int fb = __float_as_uint(col[i]);   // softmax gates > 0
        keys[i] = ((unsigned long long)fb << 32) | (unsigned int)(~i);
    }
    if (tid == 0) { s_done = 0; s_need = CC; s_prefix = 0ULL; }
    __syncthreads();

    // MSD radix select, 8-bit digits. Exits when candidate set <= 512.
    for (int shift = 56; shift >= 0; shift -= 8) {
        if (s_done) break;
        const unsigned long long pf = s_prefix;
        const int need = s_need;
        if (tid < 256) hist[tid] = 0;
        __syncthreads();
        for (int i = tid; i < SS; i += 512) {
            unsigned long long k = keys[i];
            bool active = (shift == 56) || ((k >> (shift + 8)) == pf);
            if (active) atomicAdd(&hist[(int)((k >> shift) & 255)], 1);
        }
        __syncthreads();

        // Parallel suffix sum over 256 bins (Hillis-Steele, 8 rounds).
#pragma unroll
        for (int off = 1; off < 256; off <<= 1) {
            int v = 0;
            if (tid < 256) {
                v = hist[tid];
                if (tid + off < 256) v += hist[tid + off];
            }
            __syncthreads();
            if (tid < 256) hist[tid] = v;
            __syncthreads();
        }

        // Exactly one bin d satisfies sfx[d] >= need > sfx[d+1].
        if (tid < 256) {
            int c     = hist[tid];
            int above = (tid == 255) ? 0 : hist[tid + 1];
            if (c >= need && above < need) {
                int got = (CC - need) + c;
                unsigned long long np = (pf << 8) | (unsigned long long)tid;
                if (got <= 512 || shift == 0) {
                    s_thresh = np << shift;
                    s_done = 1;
                } else {
                    s_need = need - above;
                    s_prefix = np;
                }
            }
        }
        __syncthreads();
    }

    // Collect candidates (>= threshold); pad with 0 (all real keys > 0).
    cand[tid & 511] = 0ULL;
    if (tid == 0) s_cnt = 0;
    __syncthreads();
    {
        const unsigned long long T = s_thresh;
        for (int i = tid; i < SS; i += 512) {
            unsigned long long k = keys[i];
            if (k >= T) { int p = atomicAdd(&s_cnt, 1); if (p < 512) cand[p] = k; }
        }
    }
    __syncthreads();

    // Adaptive bitonic sort (descending): nsort = next pow2 >= max(cnt, 64).
    int cnt = s_cnt;
    int nsort = 64;
    while (nsort < cnt && nsort < 512) nsort <<= 1;

    for (int k2 = 2; k2 <= nsort; k2 <<= 1) {
        for (int j = k2 >> 1; j > 0; j >>= 1) {
            if (tid < (nsort >> 1)) {
                int i   = ((tid & ~(j - 1)) << 1) | (tid & (j - 1));
                int ixj = i | j;
                bool desc = ((i & k2) == 0);
                unsigned long long a = cand[i];
                unsigned long long c = cand[ixj];
                if ((a < c) == desc) { cand[i] = c; cand[ixj] = a; }
            }
            __syncthreads();
        }
    }

    // Scatter top-64 (rank = c)
    if (tid < CC) {
        unsigned long long k = cand[tid];
        int   s = (int)(~(unsigned int)k);
        float v = __uint_as_float((unsigned int)(k >> 32));
        size_t idx = ((((size_t)b * SS + s) * EE + e) << 6) + tid;
        mask_out[idx] = 1.0f;
        comb_out[idx] = v;
    }
}

// ---------------------------------------------------------------------------
extern "C" void kernel_launch(void* const* d_in, const int* in_sizes, int n_in,
                              void* d_out, int out_size)
{
    const float* X     = (const float*)d_in[0];   // [B,S,D]
    const float* W     = (const float*)d_in[1];   // [D,E]
    const float* noise = (const float*)d_in[2];   // [B,S,E]
    float* out = (float*)d_out;

    gemm_zero_softmax_kernel<<<GBLOCKS, 256>>>(X, W, noise, (float4*)out);
    topk_kernel<<<BB * EE, 512>>>(out, out + HALF);
}